// round 9
// baseline (speedup 1.0000x reference)
#include <cuda_runtime.h>
#include <cuda_bf16.h>
#include <cstdint>

// Problem constants
#define BB 2
#define CC 64
#define NN 9216
#define CQD 8
#define NSPLIT 4
#define KEYS_PER_SPLIT (NN / NSPLIT)            // 2304
#define KT 64                                    // keys per tile
#define TILES_PER_SPLIT (KEYS_PER_SPLIT / KT)    // 36
#define QBLK 128
#define VP 72                                    // Vs row pitch in bf16 (144 B)
#define LOG2E 1.4426950408889634f

// Scratch (device globals; no allocation allowed)
__device__ float g_Q[BB * NN * CQD];                        // tf32( q * log2e )
__device__ float g_K[BB * NN * CQD];                        // tf32-rounded f32
__device__ __align__(16) __nv_bfloat16 g_Vb[BB * NN * CC];  // bf16
__device__ float g_accP[NSPLIT * BB * NN * CC];             // partial O sums
__device__ float g_lP[NSPLIT * BB * NN];                    // partial exp-sums

// ---------------------------------------------------------------------------
// PTX helpers
// ---------------------------------------------------------------------------
__device__ __forceinline__ uint32_t smem_u32(const void* p) {
    return (uint32_t)__cvta_generic_to_shared(p);
}

__device__ __forceinline__ void cp_async16(uint32_t dst, const void* src) {
    asm volatile("cp.async.cg.shared.global [%0], [%1], 16;" :: "r"(dst), "l"(src));
}
#define CP_COMMIT() asm volatile("cp.async.commit_group;")
#define CP_WAIT0()  asm volatile("cp.async.wait_group 0;")

__device__ __forceinline__ void ldmatrix_x4_trans(uint32_t& r0, uint32_t& r1,
                                                  uint32_t& r2, uint32_t& r3,
                                                  uint32_t addr) {
    asm volatile("ldmatrix.sync.aligned.m8n8.x4.trans.shared.b16 {%0,%1,%2,%3}, [%4];"
                 : "=r"(r0), "=r"(r1), "=r"(r2), "=r"(r3) : "r"(addr));
}

// bf16 PV mma: D(16x8) += A(16x16) * B(16x8)
__device__ __forceinline__ void mma16816(float& c0, float& c1, float& c2, float& c3,
                                         uint32_t a0, uint32_t a1, uint32_t a2, uint32_t a3,
                                         uint32_t b0, uint32_t b1) {
    asm volatile(
        "mma.sync.aligned.m16n8k16.row.col.f32.bf16.bf16.f32 "
        "{%0,%1,%2,%3}, {%4,%5,%6,%7}, {%8,%9}, {%0,%1,%2,%3};"
        : "+f"(c0), "+f"(c1), "+f"(c2), "+f"(c3)
        : "r"(a0), "r"(a1), "r"(a2), "r"(a3), "r"(b0), "r"(b1));
}

// tf32 QK mma: D(16x8) = A(16x8) * B(8x8)   (single k-step)
__device__ __forceinline__ void mma_tf32(float& c0, float& c1, float& c2, float& c3,
                                         uint32_t a0, uint32_t a1, uint32_t a2, uint32_t a3,
                                         uint32_t b0, uint32_t b1) {
    asm volatile(
        "mma.sync.aligned.m16n8k8.row.col.f32.tf32.tf32.f32 "
        "{%0,%1,%2,%3}, {%4,%5,%6,%7}, {%8,%9}, {%0,%1,%2,%3};"
        : "+f"(c0), "+f"(c1), "+f"(c2), "+f"(c3)
        : "r"(a0), "r"(a1), "r"(a2), "r"(a3), "r"(b0), "r"(b1));
}

// tf32 conversion: destination is a b32 register
__device__ __forceinline__ float to_tf32(float x) {
    uint32_t y;
    asm("cvt.rna.tf32.f32 %0, %1;" : "=r"(y) : "f"(x));
    return __uint_as_float(y);
}

// raw MUFU exp2
__device__ __forceinline__ float ex2(float x) {
    float y;
    asm("ex2.approx.f32 %0, %1;" : "=f"(y) : "f"(x));
    return y;
}

// ---------------------------------------------------------------------------
// Kernel 1: 1x1-conv projections.
// grid (72, B, 4), 128 threads; thread = one pixel; z picks 20 of 80 outputs.
// X row held in registers (fast round-6 body); 576 blocks ~ 3.9/SM.
// q stored as tf32(q*log2e); k tf32; v bf16.
// ---------------------------------------------------------------------------
__global__ __launch_bounds__(128) void proj_kernel(
    const float* __restrict__ X,
    const float* __restrict__ Wq, const float* __restrict__ bq,
    const float* __restrict__ Wk, const float* __restrict__ bk,
    const float* __restrict__ Wv, const float* __restrict__ bv)
{
    __shared__ float Ws[20 * 64];
    __shared__ float bs[20];

    const int t = threadIdx.x;
    const int b = blockIdx.y;
    const int z = blockIdx.z;
    const int n = blockIdx.x * 128 + t;
    const int obase = z * 20;

    for (int i = t; i < 20 * 64; i += 128) {
        const int o = obase + (i >> 6), c = i & 63;
        Ws[i] = (o < 8) ? Wq[o * 64 + c]
              : (o < 16) ? Wk[(o - 8) * 64 + c]
                         : Wv[(o - 16) * 64 + c];
    }
    if (t < 20) {
        const int o = obase + t;
        bs[t] = (o < 8) ? bq[o] : (o < 16) ? bk[o - 8] : bv[o - 16];
    }

    float x[64];
    const float* Xb = X + (size_t)b * CC * NN + n;
#pragma unroll
    for (int c = 0; c < 64; ++c) x[c] = Xb[(size_t)c * NN];

    __syncthreads();

    float* qrow = &g_Q[(size_t)(b * NN + n) * CQD];
    float* krow = &g_K[(size_t)(b * NN + n) * CQD];
    __nv_bfloat16* vrow = &g_Vb[(size_t)(b * NN + n) * CC];

    const float4* Ws4 = (const float4*)Ws;
#pragma unroll 4
    for (int oo = 0; oo < 20; ++oo) {
        float a0 = bs[oo], a1 = 0.f, a2 = 0.f, a3 = 0.f;
#pragma unroll
        for (int c4 = 0; c4 < 16; c4 += 4) {
            const float4 w0 = Ws4[oo * 16 + c4 + 0];
            const float4 w1 = Ws4[oo * 16 + c4 + 1];
            const float4 w2 = Ws4[oo * 16 + c4 + 2];
            const float4 w3 = Ws4[oo * 16 + c4 + 3];
            a0 = fmaf(w0.x, x[4*c4+0],  a0); a0 = fmaf(w0.y, x[4*c4+1],  a0);
            a0 = fmaf(w0.z, x[4*c4+2],  a0); a0 = fmaf(w0.w, x[4*c4+3],  a0);
            a1 = fmaf(w1.x, x[4*c4+4],  a1); a1 = fmaf(w1.y, x[4*c4+5],  a1);
            a1 = fmaf(w1.z, x[4*c4+6],  a1); a1 = fmaf(w1.w, x[4*c4+7],  a1);
            a2 = fmaf(w2.x, x[4*c4+8],  a2); a2 = fmaf(w2.y, x[4*c4+9],  a2);
            a2 = fmaf(w2.z, x[4*c4+10], a2); a2 = fmaf(w2.w, x[4*c4+11], a2);
            a3 = fmaf(w3.x, x[4*c4+12], a3); a3 = fmaf(w3.y, x[4*c4+13], a3);
            a3 = fmaf(w3.z, x[4*c4+14], a3); a3 = fmaf(w3.w, x[4*c4+15], a3);
        }
        const float acc = (a0 + a1) + (a2 + a3);
        const int o = obase + oo;
        if (o < 8)        qrow[o]      = to_tf32(acc * LOG2E);
        else if (o < 16)  krow[o - 8]  = to_tf32(acc);
        else              vrow[o - 16] = __float2bfloat16(acc);
    }
}

// ---------------------------------------------------------------------------
// Kernel 2: partial attention — all-tensor-core, cp.async pipelined.
// grid (72, B, NSPLIT=4), 256 threads = 8 warps; warp owns 16 query rows.
// Per 64-key tile, per 16-key chunk: 2x tf32 mma (QK) + 8 EX2 + pack,
// then 4 ldmatrix.trans + 8 bf16 mma (PV).  Single barrier per tile.
// 4 blocks/SM target -> 8 warps/SMSP to hide the QK->EX2->HMMA chain.
// ---------------------------------------------------------------------------
__global__ __launch_bounds__(256, 4) void attn_partial(void)
{
    __shared__ float Ks[2][KT * 8];                  // 2 x 2 KB
    __shared__ __nv_bfloat16 Vs[2][KT * VP];         // 2 x 9 KB

    const int t    = threadIdx.x;
    const int lane = t & 31;
    const int w    = t >> 5;
    const int b    = blockIdx.y;
    const int s    = blockIdx.z;
    const int qt   = blockIdx.x;
    const int g    = lane >> 2;      // row within 8
    const int tig  = lane & 3;       // thread in group

    // Q fragment (loop-invariant)
    const float* Qb = &g_Q[(size_t)(b * NN + qt * QBLK + w * 16) * CQD];
    const uint32_t qa0 = __float_as_uint(Qb[g * CQD + tig]);
    const uint32_t qa1 = __float_as_uint(Qb[(g + 8) * CQD + tig]);
    const uint32_t qa2 = __float_as_uint(Qb[g * CQD + tig + 4]);
    const uint32_t qa3 = __float_as_uint(Qb[(g + 8) * CQD + tig + 4]);

    float C[8][4];
#pragma unroll
    for (int i = 0; i < 8; ++i)
#pragma unroll
        for (int j = 0; j < 4; ++j) C[i][j] = 0.f;
    float l0 = 0.f, l8 = 0.f;

    const int kbase0 = s * KEYS_PER_SPLIT;
    const int vrow0  = t >> 3;            // 0..31
    const int vch    = (t & 7) * 8;       // bf16 col 0..56

    const uint32_t ks_u32[2] = { smem_u32(Ks[0]), smem_u32(Ks[1]) };
    const uint32_t vs_u32[2] = { smem_u32(Vs[0]), smem_u32(Vs[1]) };
    const uint32_t b_off = (lane & 15) * (VP * 2) + (lane >> 4) * 16;

    // stage one KT=64 tile: K = 2KB (128 x 16B), V = 8KB (512 x 16B)
#define STAGE(TILE, BUF)                                                             \
    do {                                                                             \
        const size_t kb_ = (size_t)(b * NN + kbase0 + (TILE) * KT);                  \
        if (t < 128)                                                                 \
            cp_async16(ks_u32[BUF] + t * 16, (const char*)&g_K[kb_ * CQD] + t * 16); \
        cp_async16(vs_u32[BUF] + (vrow0 * VP + vch) * 2,                             \
                   &g_Vb[(kb_ + vrow0) * CC + vch]);                                 \
        cp_async16(vs_u32[BUF] + ((vrow0 + 32) * VP + vch) * 2,                      \
                   &g_Vb[(kb_ + vrow0 + 32) * CC + vch]);                            \
    } while (0)

    STAGE(0, 0);
    CP_COMMIT();

    for (int tile = 0; tile < TILES_PER_SPLIT; ++tile) {
        const int cur = tile & 1;

        CP_WAIT0();
        __syncthreads();          // buffer cur staged; prev tile's compute done by all

        if (tile + 1 < TILES_PER_SPLIT) {
            STAGE(tile + 1, cur ^ 1);
            CP_COMMIT();
        }

        const float* KsC = Ks[cur];
        const uint32_t b_base = vs_u32[cur] + b_off;

#pragma unroll
        for (int kc = 0; kc < 4; ++kc) {
            // ---- QK (2 tf32 mma) + EX2 + pack -> A-frags ----
            uint32_t a0, a1, a2, a3;
            {
                const int ct = 2 * kc;
                const uint32_t kb0 = __float_as_uint(KsC[(8 * ct + g) * 8 + tig]);
                const uint32_t kb1 = __float_as_uint(KsC[(8 * ct + g) * 8 + tig + 4]);
                float c0 = 0.f, c1 = 0.f, c2 = 0.f, c3 = 0.f;
                mma_tf32(c0, c1, c2, c3, qa0, qa1, qa2, qa3, kb0, kb1);
                const float e0 = ex2(c0), e1 = ex2(c1), e2 = ex2(c2), e3 = ex2(c3);
                l0 += e0 + e1; l8 += e2 + e3;
                const __nv_bfloat162 p01 = __floats2bfloat162_rn(e0, e1);
                const __nv_bfloat162 p23 = __floats2bfloat162_rn(e2, e3);
                a0 = *(const uint32_t*)&p01;
                a1 = *(const uint32_t*)&p23;
            }
            {
                const int ct = 2 * kc + 1;
                const uint32_t kb0 = __float_as_uint(KsC[(8 * ct + g) * 8 + tig]);
                const uint32_t kb1 = __float_as_uint(KsC[(8 * ct + g) * 8 + tig + 4]);
                float c0 = 0.f, c1 = 0.f, c2 = 0.f, c3 = 0.f;
                mma_tf32(c0, c1, c2, c3, qa0, qa1, qa2, qa3, kb0, kb1);
                const float e0 = ex2(c0), e1 = ex2(c1), e2 = ex2(c2), e3 = ex2(c3);
                l0 += e0 + e1; l8 += e2 + e3;
                const __nv_bfloat162 p01 = __floats2bfloat162_rn(e0, e1);
                const __nv_bfloat162 p23 = __floats2bfloat162_rn(e2, e3);
                a2 = *(const uint32_t*)&p01;
                a3 = *(const uint32_t*)&p23;
            }

            // ---- PV (bf16 mma) for this 16-key chunk ----
#pragma unroll
            for (int nt = 0; nt < 4; ++nt) {
                uint32_t b0, b1, b2, b3;
                ldmatrix_x4_trans(b0, b1, b2, b3,
                                  b_base + kc * 16 * (VP * 2) + nt * 32);
                mma16816(C[2 * nt][0],     C[2 * nt][1],     C[2 * nt][2],     C[2 * nt][3],
                         a0, a1, a2, a3, b0, b1);
                mma16816(C[2 * nt + 1][0], C[2 * nt + 1][1], C[2 * nt + 1][2], C[2 * nt + 1][3],
                         a0, a1, a2, a3, b2, b3);
            }
        }
        // no bottom barrier: next tile's top barrier provides the ordering
    }

    // ---- exp-sum reduce across the quad (cols) and write ----
    l0 += __shfl_xor_sync(0xffffffffu, l0, 1);
    l0 += __shfl_xor_sync(0xffffffffu, l0, 2);
    l8 += __shfl_xor_sync(0xffffffffu, l8, 1);
    l8 += __shfl_xor_sync(0xffffffffu, l8, 2);
    const int qrow = qt * QBLK + w * 16 + g;
    if (tig == 0) {
        g_lP[(s * BB + b) * NN + qrow]     = l0;
        g_lP[(s * BB + b) * NN + qrow + 8] = l8;
    }

    // ---- write O partials ----
    float* dstB = &g_accP[(size_t)(s * BB + b) * NN * CC];
    const int r0 = qrow;
    const int c0 = 2 * tig;
#pragma unroll
    for (int nt = 0; nt < 8; ++nt) {
        *(float2*)&dstB[(size_t)r0 * CC + nt * 8 + c0]       = make_float2(C[nt][0], C[nt][1]);
        *(float2*)&dstB[(size_t)(r0 + 8) * CC + nt * 8 + c0] = make_float2(C[nt][2], C[nt][3]);
    }
#undef STAGE
}

// ---------------------------------------------------------------------------
// Kernel 3: combine splits, normalize, epilogue  out = gamma*attn_out + X
// ---------------------------------------------------------------------------
__global__ __launch_bounds__(128) void attn_combine(
    const float* __restrict__ X,
    const float* __restrict__ gamma_p,
    float* __restrict__ out)
{
    const int t = threadIdx.x;
    const int b = blockIdx.y;
    const int n = blockIdx.x * QBLK + t;

    float l = 0.f;
#pragma unroll
    for (int s = 0; s < NSPLIT; ++s)
        l += g_lP[(s * BB + b) * NN + n];
    const float inv = 1.0f / l;
    const float g   = *gamma_p;

    const float* Xb = X   + (size_t)b * CC * NN + n;
    float*       Ob = out + (size_t)b * CC * NN + n;

#pragma unroll
    for (int i = 0; i < 16; ++i) {
        float4 a = make_float4(0.f, 0.f, 0.f, 0.f);
#pragma unroll
        for (int s = 0; s < NSPLIT; ++s) {
            const float4 p = ((const float4*)&g_accP[((size_t)(s * BB + b) * NN + n) * CC])[i];
            a.x += p.x; a.y += p.y; a.z += p.z; a.w += p.w;
        }
        const int c0 = 4 * i;
        Ob[(size_t)(c0 + 0) * NN] = fmaf(g, a.x * inv, Xb[(size_t)(c0 + 0) * NN]);
        Ob[(size_t)(c0 + 1) * NN] = fmaf(g, a.y * inv, Xb[(size_t)(c0 + 1) * NN]);
        Ob[(size_t)(c0 + 2) * NN] = fmaf(g, a.z * inv, Xb[(size_t)(c0 + 2) * NN]);
        Ob[(size_t)(c0 + 3) * NN] = fmaf(g, a.w * inv, Xb[(size_t)(c0 + 3) * NN]);
    }
}

// ---------------------------------------------------------------------------
// Launch
// ---------------------------------------------------------------------------
extern "C" void kernel_launch(void* const* d_in, const int* in_sizes, int n_in,
                              void* d_out, int out_size)
{
    const float* X  = (const float*)d_in[0];
    const float* Wq = (const float*)d_in[1];
    const float* bq = (const float*)d_in[2];
    const float* Wk = (const float*)d_in[3];
    const float* bk = (const float*)d_in[4];
    const float* Wv = (const float*)d_in[5];
    const float* bv = (const float*)d_in[6];
    const float* gm = (const float*)d_in[7];
    float* out = (float*)d_out;

    dim3 g1(NN / 128, BB, 4);
    proj_kernel<<<g1, 128>>>(X, Wq, bq, Wk, bk, Wv, bv);

    dim3 g2(NN / QBLK, BB, NSPLIT);
    attn_partial<<<g2, 256>>>();

    dim3 g3(NN / QBLK, BB);
    attn_combine<<<g3, 128>>>(X, gm, out);
}